// round 13
// baseline (speedup 1.0000x reference)
#include <cuda_runtime.h>
#include <cuda_bf16.h>
#include <cstdint>
#include <cstddef>

#define BSZ  64
#define TT   512
#define FEAT 1024
#define HID  1024
#define H3   3072

#define XCHK 64     // xproj k-chunk
#define XS   68     // xproj smem row stride

#define AST2 516    // recur staged-A row stride (u32), conflict-free
#define REDW (32*34)  // per-warp reduce block (floats)
#define SFS  34     // final reduce row stride

// Scratch for x-projections: pre[m][n]
__device__ float g_pre[(size_t)BSZ * TT * H3];
// bf16 shadow state: h and (r.*h), packed 2 per u32  [64 rows][512 u32]
__device__ uint32_t g_hb [(size_t)BSZ * HID / 2];
__device__ uint32_t g_rhb[(size_t)BSZ * HID / 2];

// barrier state: per-block epoch counters (one 128B line each) + init barrier
__device__ __align__(128) unsigned g_flags[128 * 32];
__device__ __align__(128) unsigned g_icount[32];
__device__ __align__(128) unsigned g_igen[32];

// ---------- helpers ----------
__device__ __forceinline__ float sigmoidf_(float v) {
    return 1.0f / (1.0f + expf(-v));
}
__device__ __forceinline__ uint32_t cvt_tf32(float x) {
    uint32_t r;
    asm("cvt.rna.tf32.f32 %0, %1;" : "=r"(r) : "f"(x));
    return r;
}
__device__ __forceinline__ uint32_t pack_bf16(float lo, float hi) {
    __nv_bfloat162 v = __floats2bfloat162_rn(lo, hi);
    return *reinterpret_cast<uint32_t*>(&v);
}
__device__ __forceinline__ void mma_tf32(float* c, const uint32_t* a,
                                         const uint32_t* b) {
    asm volatile(
        "mma.sync.aligned.m16n8k8.row.col.f32.tf32.tf32.f32 "
        "{%0,%1,%2,%3}, {%4,%5,%6,%7}, {%8,%9}, {%0,%1,%2,%3};"
        : "+f"(c[0]), "+f"(c[1]), "+f"(c[2]), "+f"(c[3])
        : "r"(a[0]), "r"(a[1]), "r"(a[2]), "r"(a[3]),
          "r"(b[0]), "r"(b[1]));
}
__device__ __forceinline__ void mma_bf16(float* c, const uint32_t* a,
                                         const uint32_t* b) {
    asm volatile(
        "mma.sync.aligned.m16n8k16.row.col.f32.bf16.bf16.f32 "
        "{%0,%1,%2,%3}, {%4,%5,%6,%7}, {%8,%9}, {%0,%1,%2,%3};"
        : "+f"(c[0]), "+f"(c[1]), "+f"(c[2]), "+f"(c[3])
        : "r"(a[0]), "r"(a[1]), "r"(a[2]), "r"(a[3]),
          "r"(b[0]), "r"(b[1]));
}
__device__ __forceinline__ unsigned ld_acq(const unsigned* p) {
    unsigned v;
    asm volatile("ld.acquire.gpu.global.u32 %0, [%1];" : "=r"(v) : "l"(p));
    return v;
}
__device__ __forceinline__ void st_rel(unsigned* p, unsigned v) {
    asm volatile("st.release.gpu.global.u32 [%0], %1;" :: "l"(p), "r"(v));
}
__device__ __forceinline__ void cpasync16(uint32_t saddr, const void* gaddr) {
    asm volatile("cp.async.cg.shared.global [%0], [%1], 16;"
                 :: "r"(saddr), "l"(gaddr));
}
__device__ __forceinline__ void cpcommit() {
    asm volatile("cp.async.commit_group;");
}
template <int N> __device__ __forceinline__ void cpwait() {
    asm volatile("cp.async.wait_group %0;" :: "n"(N));
}

// atomic sense-reversing barrier (init only; replay-safe)
__device__ __forceinline__ void swsync(unsigned* cnt, unsigned* gen, int n) {
    __syncthreads();
    if (threadIdx.x == 0) {
        __threadfence();
        const unsigned my = ld_acq(gen);
        if (atomicAdd(cnt, 1) == (unsigned)(n - 1)) {
            *cnt = 0;
            st_rel(gen, my + 1);
        } else {
            while (ld_acq(gen) == my) { }
        }
    }
    __syncthreads();
}

extern __shared__ float smem_dyn[];

// =====================================================================
// Kernel 1: x projections (tf32 mma.sync) — unchanged.
// =====================================================================
__global__ __launch_bounds__(256) void xproj_kernel(
    const float* __restrict__ x,
    const float* __restrict__ wz, const float* __restrict__ wr,
    const float* __restrict__ wh,
    const float* __restrict__ bz, const float* __restrict__ br,
    const float* __restrict__ bh, int m_off)
{
    float* sx  = smem_dyn;                 // [2][64][XS]
    float* swt = smem_dyn + 2 * 64 * XS;   // [2][64][XS]

    const int tid = threadIdx.x;
    const int n0  = blockIdx.x * 64;
    const int m0  = (m_off + blockIdx.y) * 64;

    const int gate = n0 >> 10;
    const int ng   = n0 & 1023;
    const float* wptr = (gate == 0) ? wz : (gate == 1) ? wr : wh;
    const float* bptr = (gate == 0) ? bz : (gate == 1) ? br : bh;

    const int w  = tid >> 5;
    const int l  = tid & 31;
    const int kw = w >> 2;
    const int mw = (w >> 1) & 1;
    const int nw = w & 1;

    float c[2][4][4];
#pragma unroll
    for (int mt = 0; mt < 2; mt++)
#pragma unroll
        for (int nt = 0; nt < 4; nt++)
#pragma unroll
            for (int r = 0; r < 4; r++) c[mt][nt][r] = 0.0f;

    const int s_row = tid >> 4;
    const int s_q   = tid & 15;

    auto stage = [&](int buf, int k0) {
#pragma unroll
        for (int i = 0; i < 4; i++) {
            int row = s_row + 16 * i;
            uint32_t sa = (uint32_t)__cvta_generic_to_shared(
                sx + buf * 64 * XS + row * XS + 4 * s_q);
            cpasync16(sa, x + (size_t)(m0 + row) * FEAT + k0 + 4 * s_q);
        }
#pragma unroll
        for (int i = 0; i < 4; i++) {
            int kr = s_row + 16 * i;
            uint32_t sa = (uint32_t)__cvta_generic_to_shared(
                swt + buf * 64 * XS + kr * XS + 4 * s_q);
            cpasync16(sa, wptr + (size_t)(1024 + k0 + kr) * HID + ng + 4 * s_q);
        }
        cpcommit();
    };

    const int ar = l >> 2, ac = l & 3;
    const int bk = l & 3,  bn = l >> 2;

    stage(0, 0);
    for (int ch = 0; ch < FEAT / XCHK; ch++) {
        if (ch + 1 < FEAT / XCHK) {
            stage((ch + 1) & 1, (ch + 1) * XCHK);
            cpwait<1>();
        } else {
            cpwait<0>();
        }
        __syncthreads();

        const float* SX = sx  + (ch & 1) * 64 * XS;
        const float* SW = swt + (ch & 1) * 64 * XS;

#pragma unroll
        for (int kt = 0; kt < 4; kt++) {
            const int k = kw * 32 + kt * 8;

            uint32_t a[2][4];
#pragma unroll
            for (int mt = 0; mt < 2; mt++) {
                const float* P = SX + (mw * 32 + mt * 16 + ar) * XS + k + ac;
                a[mt][0] = cvt_tf32(P[0]);
                a[mt][1] = cvt_tf32(P[8 * XS]);
                a[mt][2] = cvt_tf32(P[4]);
                a[mt][3] = cvt_tf32(P[8 * XS + 4]);
            }
            uint32_t b[4][2];
#pragma unroll
            for (int nt = 0; nt < 4; nt++) {
                const float* Q = SW + (k + bk) * XS + nw * 32 + nt * 8 + bn;
                b[nt][0] = cvt_tf32(Q[0]);
                b[nt][1] = cvt_tf32(Q[4 * XS]);
            }
#pragma unroll
            for (int mt = 0; mt < 2; mt++)
#pragma unroll
                for (int nt = 0; nt < 4; nt++)
                    mma_tf32(c[mt][nt], a[mt], b[nt]);
        }
        __syncthreads();
    }

    float* sred = smem_dyn;
    if (kw == 1) {
        float* dst = sred + (mw * 2 + nw) * 1024;
#pragma unroll
        for (int mt = 0; mt < 2; mt++)
#pragma unroll
            for (int nt = 0; nt < 4; nt++)
#pragma unroll
                for (int r = 0; r < 4; r++) {
                    int row = mt * 16 + (l >> 2) + (r >= 2 ? 8 : 0);
                    int col = nt * 8 + 2 * (l & 3) + (r & 1);
                    dst[row * 32 + col] = c[mt][nt][r];
                }
    }
    __syncthreads();
    if (kw == 0) {
        const float* src = sred + (mw * 2 + nw) * 1024;
#pragma unroll
        for (int mt = 0; mt < 2; mt++)
#pragma unroll
            for (int nt = 0; nt < 4; nt++) {
#pragma unroll
                for (int r = 0; r < 4; r++) {
                    int row = mt * 16 + (l >> 2) + (r >= 2 ? 8 : 0);
                    int col = nt * 8 + 2 * (l & 3) + (r & 1);
                    c[mt][nt][r] += src[row * 32 + col];
                }
#pragma unroll
                for (int half = 0; half < 2; half++) {
                    const int row = mt * 16 + (l >> 2) + 8 * half;
                    const int nbase = nw * 32 + nt * 8 + 2 * (l & 3);
                    float2 v;
                    v.x = c[mt][nt][2 * half + 0] + bptr[ng + nbase];
                    v.y = c[mt][nt][2 * half + 1] + bptr[ng + nbase + 1];
                    *(float2*)&g_pre[(size_t)(m0 + mw * 32 + row) * H3 + n0 + nbase] = v;
                }
            }
    }
}

// =====================================================================
// Kernel 2: persistent recurrence — interleaved dual-chain pipeline.
// 128 blocks x 256 threads; block owns 8 h-cols x BOTH batch halves.
// Per step: A0(r,z half0) arr | A1 arr | wait rh0, B0(hbar) arr |
//           wait rh1, B1 arr.  Inter-block waits hidden by other chain.
// Per-block monotone epoch flags; 4 arrivals/step.
// =====================================================================
__global__ __launch_bounds__(256, 1) void recur_kernel(
    const float* __restrict__ h0,
    const float* __restrict__ wz, const float* __restrict__ wr,
    const float* __restrict__ wh,
    float* __restrict__ out)
{
    uint32_t* sP0  = (uint32_t*)smem_dyn;           // [32][AST2]
    uint32_t* sP1  = sP0 + 32 * AST2;               // [32][AST2]
    float*    sred = smem_dyn + 2 * 32 * AST2;      // [8][32][34]
    float*    sfin = sred + 8 * REDW;               // [32][SFS]

    const int tid = threadIdx.x;
    const int w   = tid >> 5;
    const int l   = tid & 31;
    const int j0  = blockIdx.x * 8;            // 8 cols per block

    const int ar = l >> 2, ac = l & 3;        // A-frag coords
    const int bk = l & 3,  bn = l >> 2;       // B-frag coords

    // ---- one-time: bf16 B fragments (k-slice 128w, n=8) ----
    uint32_t bzf[8][2], brf[8][2], bhf[8][2];
#pragma unroll
    for (int kt = 0; kt < 8; kt++)
#pragma unroll
        for (int h = 0; h < 2; h++) {
            const int k0 = 128 * w + 16 * kt + 2 * bk + 8 * h;
            const int n  = j0 + bn;
            bzf[kt][h] = pack_bf16(wz[(size_t)k0 * HID + n], wz[(size_t)(k0 + 1) * HID + n]);
            brf[kt][h] = pack_bf16(wr[(size_t)k0 * HID + n], wr[(size_t)(k0 + 1) * HID + n]);
            bhf[kt][h] = pack_bf16(wh[(size_t)k0 * HID + n], wh[(size_t)(k0 + 1) * HID + n]);
        }

    // ---- one-time: reset own flag, h0 -> bf16 shadow, init barrier ----
    if (tid == 0) g_flags[blockIdx.x * 32] = 0;
    {
        const int idx = blockIdx.x * 256 + tid;    // 32768 u32 total
        g_hb[idx] = pack_bf16(h0[2 * idx], h0[2 * idx + 1]);
    }
    swsync(&g_icount[0], &g_igen[0], 128);

    // wait until every block's epoch >= target
    auto waitf = [&](unsigned target) {
        if (tid < 128) {
            const unsigned* f = &g_flags[tid * 32];
            while (ld_acq(f) < target) { }
        }
        __syncthreads();
    };
    // publish this block's epoch
    auto arrive = [&](unsigned val) {
        __syncthreads();
        if (tid == 0) {
            __threadfence();
            st_rel(&g_flags[blockIdx.x * 32], val);
        }
    };

    // elementwise mapping (tid < 128): row eb, col pair ec0
    const int eb  = tid >> 2;                  // 0..31
    const int ec0 = (tid & 3) * 2;             // 0,2,4,6

    // stage half hf (32 rows x 512 u32) into buffer
    auto stageA = [&](uint32_t* dstb, const uint32_t* srcu, int hf) {
        const uint32_t* base = srcu + (size_t)hf * 32 * 512;
#pragma unroll
        for (int it = 0; it < 16; it++) {
            int idx = tid + it * 256;
            int row = idx >> 7;                // 0..31
            int q   = idx & 127;
            uint32_t sa = (uint32_t)__cvta_generic_to_shared(dstb + row * AST2 + 4 * q);
            cpasync16(sa, base + (size_t)row * 512 + 4 * q);
        }
        cpcommit();
    };

    // GEMM pass A (r+z) over buffer
    auto passA = [&](const uint32_t* buf, float aR[2][4], float aZ[2][4]) {
#pragma unroll
        for (int mt = 0; mt < 2; mt++)
#pragma unroll
            for (int r = 0; r < 4; r++) { aR[mt][r] = 0.0f; aZ[mt][r] = 0.0f; }
#pragma unroll
        for (int kt = 0; kt < 8; kt++) {
            const int ko = 64 * w + 8 * kt;
#pragma unroll
            for (int mt = 0; mt < 2; mt++) {
                const uint32_t* P = buf + (16 * mt + ar) * AST2 + ko + ac;
                uint32_t a[4];
                a[0] = P[0];
                a[1] = P[8 * AST2];
                a[2] = P[4];
                a[3] = P[8 * AST2 + 4];
                mma_bf16(aR[mt], a, brf[kt]);
                mma_bf16(aZ[mt], a, bzf[kt]);
            }
        }
    };
    // GEMM pass B (hbar)
    auto passB = [&](const uint32_t* buf, float aH[2][4]) {
#pragma unroll
        for (int mt = 0; mt < 2; mt++)
#pragma unroll
            for (int r = 0; r < 4; r++) aH[mt][r] = 0.0f;
#pragma unroll
        for (int kt = 0; kt < 8; kt++) {
            const int ko = 64 * w + 8 * kt;
#pragma unroll
            for (int mt = 0; mt < 2; mt++) {
                const uint32_t* P = buf + (16 * mt + ar) * AST2 + ko + ac;
                uint32_t a[4];
                a[0] = P[0];
                a[1] = P[8 * AST2];
                a[2] = P[4];
                a[3] = P[8 * AST2 + 4];
                mma_bf16(aH[mt], a, bhf[kt]);
            }
        }
    };

    float zv[2][2];                            // z per half per col

    for (int t = 0; t < TT; t++) {
        const float* hprev = (t == 0) ? h0 : (out + (size_t)(t - 1) * HID);
        const long   hstr  = (t == 0) ? (long)HID : (long)TT * HID;
        const unsigned e0  = 4u * (unsigned)t;

        // ---- stage both halves' h (h0 ready at e0-1, h1 at e0) ----
        if (t) waitf(e0 - 1);
        stageA(sP0, g_hb, 0);                  // group: P0
        if (t) waitf(e0);
        stageA(sP1, g_hb, 1);                  // group: P1

        // pointwise prefetch (own cols — no cross-block dependency)
        float2 xzv[2], xrv[2], xhv[2], hpv[2];
        if (tid < 128) {
#pragma unroll
            for (int hf = 0; hf < 2; hf++) {
                const int gb = hf * 32 + eb;
                const float* pp = g_pre + (size_t)(gb * TT + t) * H3 + j0 + ec0;
                xzv[hf] = __ldg((const float2*)pp);
                xrv[hf] = __ldg((const float2*)(pp + 1024));
                xhv[hf] = __ldg((const float2*)(pp + 2048));
                hpv[hf] = __ldcg((const float2*)(hprev + (size_t)gb * hstr + j0 + ec0));
            }
        }

        // ================= A-phases: r,z for each half =================
#pragma unroll
        for (int hf = 0; hf < 2; hf++) {
            if (hf == 0) cpwait<1>(); else cpwait<0>();
            __syncthreads();

            float aR[2][4], aZ[2][4];
            passA(hf == 0 ? sP0 : sP1, aR, aZ);

            // reduce r (cols 0..7) + z (cols 8..15)
            {
                float* dst = sred + w * REDW;
#pragma unroll
                for (int mt = 0; mt < 2; mt++) {
                    int r0 = 16 * mt + (l >> 2);
                    int c0 = 2 * (l & 3);
                    dst[r0 * 34 + c0]           = aR[mt][0];
                    dst[r0 * 34 + c0 + 1]       = aR[mt][1];
                    dst[(r0 + 8) * 34 + c0]     = aR[mt][2];
                    dst[(r0 + 8) * 34 + c0 + 1] = aR[mt][3];
                    dst[r0 * 34 + 8 + c0]           = aZ[mt][0];
                    dst[r0 * 34 + 8 + c0 + 1]       = aZ[mt][1];
                    dst[(r0 + 8) * 34 + 8 + c0]     = aZ[mt][2];
                    dst[(r0 + 8) * 34 + 8 + c0 + 1] = aZ[mt][3];
                }
            }
            __syncthreads();
            {
                int b = tid >> 3, n = (tid & 7) * 2;   // 32 x 16, 2/thread
                float s0 = 0.0f, s1 = 0.0f;
#pragma unroll
                for (int ww = 0; ww < 8; ww++) {
                    const float* src = sred + ww * REDW + b * 34 + n;
                    s0 += src[0]; s1 += src[1];
                }
                sfin[b * SFS + n] = s0;
                sfin[b * SFS + n + 1] = s1;
            }
            __syncthreads();

            // elementwise: z -> regs, rh -> global
            if (tid < 128) {
                const int gb = hf * 32 + eb;
                const float hp[2] = {hpv[hf].x, hpv[hf].y};
                const float xr[2] = {xrv[hf].x, xrv[hf].y};
                const float xz[2] = {xzv[hf].x, xzv[hf].y};
                float rhv[2];
#pragma unroll
                for (int j = 0; j < 2; j++) {
                    const float r = sigmoidf_(sfin[eb * SFS + ec0 + j] + xr[j]);
                    zv[hf][j] = sigmoidf_(sfin[eb * SFS + 8 + ec0 + j] + xz[j]);
                    rhv[j] = r * hp[j];
                }
                g_rhb[(size_t)gb * 512 + ((j0 + ec0) >> 1)] = pack_bf16(rhv[0], rhv[1]);
            }
            arrive(e0 + 1 + hf);               // rh(hf) published
        }

        // ================= B-phases: hbar + update for each half =================
#pragma unroll
        for (int hf = 0; hf < 2; hf++) {
            waitf(e0 + 1 + hf);                // all rh(hf) ready
            stageA(hf == 0 ? sP0 : sP1, g_rhb, hf);
            cpwait<0>();
            __syncthreads();

            float aH[2][4];
            passB(hf == 0 ? sP0 : sP1, aH);

            // reduce hbar (cols 0..7)
            {
                float* dst = sred + w * REDW;
#pragma unroll
                for (int mt = 0; mt < 2; mt++) {
                    int r0 = 16 * mt + (l >> 2);
                    int c0 = 2 * (l & 3);
                    dst[r0 * 34 + c0]           = aH[mt][0];
                    dst[r0 * 34 + c0 + 1]       = aH[mt][1];
                    dst[(r0 + 8) * 34 + c0]     = aH[mt][2];
                    dst[(r0 + 8) * 34 + c0 + 1] = aH[mt][3];
                }
            }
            __syncthreads();
            {
                int b = tid >> 3, n = tid & 7;     // 32 x 8, 1/thread
                float s = 0.0f;
#pragma unroll
                for (int ww = 0; ww < 8; ww++) s += sred[ww * REDW + b * 34 + n];
                sfin[b * SFS + n] = s;
            }
            __syncthreads();

            // elementwise: h update + outputs
            if (tid < 128) {
                const int gb = hf * 32 + eb;
                const float hp[2] = {hpv[hf].x, hpv[hf].y};
                const float xh[2] = {xhv[hf].x, xhv[hf].y};
                float hn[2];
#pragma unroll
                for (int j = 0; j < 2; j++) {
                    const float hb = tanhf(sfin[eb * SFS + ec0 + j] + xh[j]);
                    hn[j] = (1.0f - zv[hf][j]) * hp[j] + zv[hf][j] * hb;
                }
                float2 o; o.x = hn[0]; o.y = hn[1];
                *(float2*)&out[((size_t)gb * TT + t) * HID + j0 + ec0] = o;
                g_hb[(size_t)gb * 512 + ((j0 + ec0) >> 1)] = pack_bf16(hn[0], hn[1]);
                if (t == TT - 1)
                    *(float2*)&out[(size_t)BSZ * TT * HID + (size_t)gb * HID + j0 + ec0] = o;
            }
            if (t + 1 < TT)
                arrive(e0 + 3 + hf);           // h(hf) published
        }
    }
}

// =====================================================================
extern "C" void kernel_launch(void* const* d_in, const int* in_sizes, int n_in,
                              void* d_out, int out_size)
{
    const float* x  = (const float*)d_in[0];
    const float* h0 = (const float*)d_in[1];
    const float* wz = (const float*)d_in[2];
    const float* wr = (const float*)d_in[3];
    const float* wh = (const float*)d_in[4];
    const float* bz = (const float*)d_in[5];
    const float* br = (const float*)d_in[6];
    const float* bh = (const float*)d_in[7];
    float* out = (float*)d_out;

    const int x_smem = 4 * 64 * XS * sizeof(float);
    const int r_smem = (2 * 32 * AST2 + 8 * REDW + 32 * SFS) * sizeof(float);
    static bool attr_set = false;
    if (!attr_set) {
        cudaFuncSetAttribute(xproj_kernel,
                             cudaFuncAttributeMaxDynamicSharedMemorySize, x_smem);
        cudaFuncSetAttribute(recur_kernel,
                             cudaFuncAttributeMaxDynamicSharedMemorySize, r_smem);
        attr_set = true;
    }

    const int ysplit[4] = {0, 171, 342, 512};
    for (int s = 0; s < 3; s++) {
        dim3 g1(H3 / 64, ysplit[s + 1] - ysplit[s]);
        xproj_kernel<<<g1, 256, x_smem>>>(x, wz, wr, wh, bz, br, bh, ysplit[s]);
    }

    recur_kernel<<<128, 256, r_smem>>>(h0, wz, wr, wh, out);
}

// round 14
// speedup vs baseline: 1.4239x; 1.4239x over previous
#include <cuda_runtime.h>
#include <cuda_bf16.h>
#include <cstdint>
#include <cstddef>

#define BSZ  64
#define TT   512
#define FEAT 1024
#define HID  1024
#define H3   3072

#define XCHK 64     // xproj k-chunk
#define XS   68     // xproj smem row stride

#define AST2 516    // recur staged-A row stride (u32), conflict-free
#define REDW (32*34)  // per-warp reduce block (floats)
#define SFS  34     // final reduce row stride

// Scratch for x-projections: pre[m][n]
__device__ float g_pre[(size_t)BSZ * TT * H3];
// bf16 shadow state: h and (r.*h), packed 2 per u32  [64 rows][512 u32]
__device__ uint32_t g_hb [(size_t)BSZ * HID / 2];
__device__ uint32_t g_rhb[(size_t)BSZ * HID / 2];

// barrier state: per-block epoch flags (one 128B line each) + init barrier
__device__ __align__(128) unsigned g_flags[128 * 32];
__device__ __align__(128) unsigned g_icount[32];
__device__ __align__(128) unsigned g_igen[32];

// ---------- helpers ----------
__device__ __forceinline__ float sigmoidf_(float v) {
    return 1.0f / (1.0f + expf(-v));
}
__device__ __forceinline__ uint32_t cvt_tf32(float x) {
    uint32_t r;
    asm("cvt.rna.tf32.f32 %0, %1;" : "=r"(r) : "f"(x));
    return r;
}
__device__ __forceinline__ uint32_t pack_bf16(float lo, float hi) {
    __nv_bfloat162 v = __floats2bfloat162_rn(lo, hi);
    return *reinterpret_cast<uint32_t*>(&v);
}
__device__ __forceinline__ void mma_tf32(float* c, const uint32_t* a,
                                         const uint32_t* b) {
    asm volatile(
        "mma.sync.aligned.m16n8k8.row.col.f32.tf32.tf32.f32 "
        "{%0,%1,%2,%3}, {%4,%5,%6,%7}, {%8,%9}, {%0,%1,%2,%3};"
        : "+f"(c[0]), "+f"(c[1]), "+f"(c[2]), "+f"(c[3])
        : "r"(a[0]), "r"(a[1]), "r"(a[2]), "r"(a[3]),
          "r"(b[0]), "r"(b[1]));
}
__device__ __forceinline__ void mma_bf16(float* c, const uint32_t* a,
                                         const uint32_t* b) {
    asm volatile(
        "mma.sync.aligned.m16n8k16.row.col.f32.bf16.bf16.f32 "
        "{%0,%1,%2,%3}, {%4,%5,%6,%7}, {%8,%9}, {%0,%1,%2,%3};"
        : "+f"(c[0]), "+f"(c[1]), "+f"(c[2]), "+f"(c[3])
        : "r"(a[0]), "r"(a[1]), "r"(a[2]), "r"(a[3]),
          "r"(b[0]), "r"(b[1]));
}
__device__ __forceinline__ unsigned ld_acq(const unsigned* p) {
    unsigned v;
    asm volatile("ld.acquire.gpu.global.u32 %0, [%1];" : "=r"(v) : "l"(p));
    return v;
}
__device__ __forceinline__ void st_rel(unsigned* p, unsigned v) {
    asm volatile("st.release.gpu.global.u32 [%0], %1;" :: "l"(p), "r"(v));
}
__device__ __forceinline__ void cpasync16(uint32_t saddr, const void* gaddr) {
    asm volatile("cp.async.cg.shared.global [%0], [%1], 16;"
                 :: "r"(saddr), "l"(gaddr));
}
__device__ __forceinline__ void cpcommit() {
    asm volatile("cp.async.commit_group;");
}
template <int N> __device__ __forceinline__ void cpwait() {
    asm volatile("cp.async.wait_group %0;" :: "n"(N));
}

// ---------- bulk-copy (UBLKCP) staging ----------
__device__ __forceinline__ void cpbulk(uint32_t sdst, const void* gsrc,
                                       unsigned bytes, uint32_t mbar) {
    asm volatile(
        "cp.async.bulk.shared::cta.global.mbarrier::complete_tx::bytes "
        "[%0], [%1], %2, [%3];"
        :: "r"(sdst), "l"(gsrc), "r"(bytes), "r"(mbar) : "memory");
}
__device__ __forceinline__ void mbar_init(uint32_t mbar, unsigned cnt) {
    asm volatile("mbarrier.init.shared.b64 [%0], %1;" :: "r"(mbar), "r"(cnt)
                 : "memory");
}
__device__ __forceinline__ void mbar_expect(uint32_t mbar, unsigned bytes) {
    asm volatile("mbarrier.arrive.expect_tx.shared.b64 _, [%0], %1;"
                 :: "r"(mbar), "r"(bytes) : "memory");
}
__device__ __forceinline__ void mbar_wait(uint32_t mbar, unsigned parity) {
    asm volatile(
        "{\n\t.reg .pred P;\n\t"
        "W0_%=:\n\t"
        "mbarrier.try_wait.parity.acquire.cta.shared::cta.b64 P, [%0], %1, 0x989680;\n\t"
        "@P bra W1_%=;\n\t"
        "bra W0_%=;\n\t"
        "W1_%=:\n\t}"
        :: "r"(mbar), "r"(parity) : "memory");
}

// atomic sense-reversing barrier (init only; replay-safe)
__device__ __forceinline__ void swsync(unsigned* cnt, unsigned* gen, int n) {
    __syncthreads();
    if (threadIdx.x == 0) {
        __threadfence();
        const unsigned my = ld_acq(gen);
        if (atomicAdd(cnt, 1) == (unsigned)(n - 1)) {
            *cnt = 0;
            st_rel(gen, my + 1);
        } else {
            while (ld_acq(gen) == my) { }
        }
    }
    __syncthreads();
}

extern __shared__ float smem_dyn[];

// =====================================================================
// Kernel 1: x projections (tf32 mma.sync) — unchanged.
// =====================================================================
__global__ __launch_bounds__(256) void xproj_kernel(
    const float* __restrict__ x,
    const float* __restrict__ wz, const float* __restrict__ wr,
    const float* __restrict__ wh,
    const float* __restrict__ bz, const float* __restrict__ br,
    const float* __restrict__ bh, int m_off)
{
    float* sx  = smem_dyn;                 // [2][64][XS]
    float* swt = smem_dyn + 2 * 64 * XS;   // [2][64][XS]

    const int tid = threadIdx.x;
    const int n0  = blockIdx.x * 64;
    const int m0  = (m_off + blockIdx.y) * 64;

    const int gate = n0 >> 10;
    const int ng   = n0 & 1023;
    const float* wptr = (gate == 0) ? wz : (gate == 1) ? wr : wh;
    const float* bptr = (gate == 0) ? bz : (gate == 1) ? br : bh;

    const int w  = tid >> 5;
    const int l  = tid & 31;
    const int kw = w >> 2;
    const int mw = (w >> 1) & 1;
    const int nw = w & 1;

    float c[2][4][4];
#pragma unroll
    for (int mt = 0; mt < 2; mt++)
#pragma unroll
        for (int nt = 0; nt < 4; nt++)
#pragma unroll
            for (int r = 0; r < 4; r++) c[mt][nt][r] = 0.0f;

    const int s_row = tid >> 4;
    const int s_q   = tid & 15;

    auto stage = [&](int buf, int k0) {
#pragma unroll
        for (int i = 0; i < 4; i++) {
            int row = s_row + 16 * i;
            uint32_t sa = (uint32_t)__cvta_generic_to_shared(
                sx + buf * 64 * XS + row * XS + 4 * s_q);
            cpasync16(sa, x + (size_t)(m0 + row) * FEAT + k0 + 4 * s_q);
        }
#pragma unroll
        for (int i = 0; i < 4; i++) {
            int kr = s_row + 16 * i;
            uint32_t sa = (uint32_t)__cvta_generic_to_shared(
                swt + buf * 64 * XS + kr * XS + 4 * s_q);
            cpasync16(sa, wptr + (size_t)(1024 + k0 + kr) * HID + ng + 4 * s_q);
        }
        cpcommit();
    };

    const int ar = l >> 2, ac = l & 3;
    const int bk = l & 3,  bn = l >> 2;

    stage(0, 0);
    for (int ch = 0; ch < FEAT / XCHK; ch++) {
        if (ch + 1 < FEAT / XCHK) {
            stage((ch + 1) & 1, (ch + 1) * XCHK);
            cpwait<1>();
        } else {
            cpwait<0>();
        }
        __syncthreads();

        const float* SX = sx  + (ch & 1) * 64 * XS;
        const float* SW = swt + (ch & 1) * 64 * XS;

#pragma unroll
        for (int kt = 0; kt < 4; kt++) {
            const int k = kw * 32 + kt * 8;

            uint32_t a[2][4];
#pragma unroll
            for (int mt = 0; mt < 2; mt++) {
                const float* P = SX + (mw * 32 + mt * 16 + ar) * XS + k + ac;
                a[mt][0] = cvt_tf32(P[0]);
                a[mt][1] = cvt_tf32(P[8 * XS]);
                a[mt][2] = cvt_tf32(P[4]);
                a[mt][3] = cvt_tf32(P[8 * XS + 4]);
            }
            uint32_t b[4][2];
#pragma unroll
            for (int nt = 0; nt < 4; nt++) {
                const float* Q = SW + (k + bk) * XS + nw * 32 + nt * 8 + bn;
                b[nt][0] = cvt_tf32(Q[0]);
                b[nt][1] = cvt_tf32(Q[4 * XS]);
            }
#pragma unroll
            for (int mt = 0; mt < 2; mt++)
#pragma unroll
                for (int nt = 0; nt < 4; nt++)
                    mma_tf32(c[mt][nt], a[mt], b[nt]);
        }
        __syncthreads();
    }

    float* sred = smem_dyn;
    if (kw == 1) {
        float* dst = sred + (mw * 2 + nw) * 1024;
#pragma unroll
        for (int mt = 0; mt < 2; mt++)
#pragma unroll
            for (int nt = 0; nt < 4; nt++)
#pragma unroll
                for (int r = 0; r < 4; r++) {
                    int row = mt * 16 + (l >> 2) + (r >= 2 ? 8 : 0);
                    int col = nt * 8 + 2 * (l & 3) + (r & 1);
                    dst[row * 32 + col] = c[mt][nt][r];
                }
    }
    __syncthreads();
    if (kw == 0) {
        const float* src = sred + (mw * 2 + nw) * 1024;
#pragma unroll
        for (int mt = 0; mt < 2; mt++)
#pragma unroll
            for (int nt = 0; nt < 4; nt++) {
#pragma unroll
                for (int r = 0; r < 4; r++) {
                    int row = mt * 16 + (l >> 2) + (r >= 2 ? 8 : 0);
                    int col = nt * 8 + 2 * (l & 3) + (r & 1);
                    c[mt][nt][r] += src[row * 32 + col];
                }
#pragma unroll
                for (int half = 0; half < 2; half++) {
                    const int row = mt * 16 + (l >> 2) + 8 * half;
                    const int nbase = nw * 32 + nt * 8 + 2 * (l & 3);
                    float2 v;
                    v.x = c[mt][nt][2 * half + 0] + bptr[ng + nbase];
                    v.y = c[mt][nt][2 * half + 1] + bptr[ng + nbase + 1];
                    *(float2*)&g_pre[(size_t)(m0 + mw * 32 + row) * H3 + n0 + nbase] = v;
                }
            }
    }
}

// =====================================================================
// Kernel 2: persistent recurrence — R12 structure + cp.async.bulk staging.
// 128 blocks x 256 threads = 2 batch-halves x 64 col-groups (16 cols).
// Flag-array half-barriers.  Stage = 32 x 2KB UBLKCP + mbarrier (single
// issuing thread) instead of 4096 x 16B LDGSTS.
// Phase A: r only (h kept in buf0).  Phase B: bulk-stage rh into buf1
// while computing z from retained h, then hbar from rh.
// =====================================================================
__global__ __launch_bounds__(256, 1) void recur_kernel(
    const float* __restrict__ h0,
    const float* __restrict__ wz, const float* __restrict__ wr,
    const float* __restrict__ wh,
    float* __restrict__ out)
{
    uint32_t* sA0  = (uint32_t*)smem_dyn;           // [32][AST2]  h
    uint32_t* sA1  = sA0 + 32 * AST2;               // [32][AST2]  rh
    float*    sred = smem_dyn + 2 * 32 * AST2;      // [8][32][34]
    float*    sfin = sred + 8 * REDW;               // [32][SFS]
    uint64_t* mb   = (uint64_t*)(sfin + 32 * SFS);  // mbarrier (8B)

    const int tid  = threadIdx.x;
    const int w    = tid >> 5;
    const int l    = tid & 31;
    const int half = blockIdx.x & 1;
    const int cg   = blockIdx.x >> 1;          // 0..63
    const int j0   = cg * 16;

    const uint32_t mbar = (uint32_t)__cvta_generic_to_shared(mb);
    const uint32_t sA0u = (uint32_t)__cvta_generic_to_shared(sA0);
    const uint32_t sA1u = (uint32_t)__cvta_generic_to_shared(sA1);

    const int ar = l >> 2, ac = l & 3;        // A-frag coords
    const int bk = l & 3,  bn = l >> 2;       // B-frag coords

    // ---- one-time: bf16 B fragments in registers (k-slice 128w, n=16) ----
    uint32_t bzf[8][2][2], brf[8][2][2], bhf[8][2][2];
#pragma unroll
    for (int kt = 0; kt < 8; kt++)
#pragma unroll
        for (int nt = 0; nt < 2; nt++)
#pragma unroll
            for (int h = 0; h < 2; h++) {
                const int k0 = 128 * w + 16 * kt + 2 * bk + 8 * h;
                const int n  = j0 + 8 * nt + bn;
                bzf[kt][nt][h] = pack_bf16(wz[(size_t)k0 * HID + n], wz[(size_t)(k0 + 1) * HID + n]);
                brf[kt][nt][h] = pack_bf16(wr[(size_t)k0 * HID + n], wr[(size_t)(k0 + 1) * HID + n]);
                bhf[kt][nt][h] = pack_bf16(wh[(size_t)k0 * HID + n], wh[(size_t)(k0 + 1) * HID + n]);
            }

    // ---- one-time: flag reset, mbarrier init, h0 -> bf16, init barrier ----
    if (tid == 0) {
        g_flags[blockIdx.x * 32] = 0;
        mbar_init(mbar, 1);
    }
    {
        const int idx = blockIdx.x * 256 + tid;    // 32768 u32 total
        g_hb[idx] = pack_bf16(h0[2 * idx], h0[2 * idx + 1]);
    }
    swsync(&g_icount[0], &g_igen[0], 128);

    // flag-array barrier over this half's 64 blocks
    unsigned ep = 0;
    auto fsync = [&]() {
        __syncthreads();
        ep++;
        if (tid == 0) {
            __threadfence();
            st_rel(&g_flags[blockIdx.x * 32], ep);
        }
        if (tid < 64) {
            const unsigned* f = &g_flags[(2 * tid + half) * 32];
            while (ld_acq(f) < ep) { }
        }
        __syncthreads();
    };

    // bulk-stage this half's 32x1024 bf16 rows (64KB) into a buffer
    unsigned mpar = 0;   // mbarrier phase parity (tracked identically per thread)
    auto stage_bulk = [&](uint32_t dstu, const uint32_t* srcu) {
        if (tid == 0) {
            mbar_expect(mbar, 32 * 2048);
            const uint32_t* base = srcu + (size_t)half * 32 * 512;
#pragma unroll
            for (int row = 0; row < 32; row++)
                cpbulk(dstu + row * (AST2 * 4), base + (size_t)row * 512,
                       2048, mbar);
        }
    };

    // elementwise mapping: thread -> (row eb, cols ec0, ec0+1)
    const int eb  = tid >> 3;
    const int ec0 = (tid & 7) * 2;
    const int gb  = half * 32 + eb;            // global batch row

    for (int t = 0; t < TT; t++) {
        const float* hprev = (t == 0) ? h0 : (out + (size_t)(t - 1) * HID);
        const long   hstr  = (t == 0) ? (long)HID : (long)TT * HID;

        // prefetch pointwise operands (fp32)
        const float* pp = g_pre + (size_t)(gb * TT + t) * H3 + j0 + ec0;
        const float2 xzv = __ldg((const float2*)pp);
        const float2 xrv = __ldg((const float2*)(pp + 1024));
        const float2 xhv = __ldg((const float2*)(pp + 2048));
        const float2 hpv = __ldcg((const float2*)(hprev + (size_t)gb * hstr + j0 + ec0));

        // ================= phase A: r gate only =================
        float aR[2][2][4];
#pragma unroll
        for (int mt = 0; mt < 2; mt++)
#pragma unroll
            for (int nt = 0; nt < 2; nt++)
#pragma unroll
                for (int r = 0; r < 4; r++) aR[mt][nt][r] = 0.0f;

        stage_bulk(sA0u, g_hb);
        mbar_wait(mbar, mpar);  mpar ^= 1;

#pragma unroll
        for (int kt = 0; kt < 8; kt++) {
            const int ko = 64 * w + 8 * kt;
#pragma unroll
            for (int mt = 0; mt < 2; mt++) {
                const uint32_t* P = sA0 + (16 * mt + ar) * AST2 + ko + ac;
                uint32_t a[4];
                a[0] = P[0];
                a[1] = P[8 * AST2];
                a[2] = P[4];
                a[3] = P[8 * AST2 + 4];
#pragma unroll
                for (int nt = 0; nt < 2; nt++)
                    mma_bf16(aR[mt][nt], a, brf[kt][nt]);
            }
        }

        // reduce r: 8 warps -> sred -> sfin cols 0..15
        {
            float* dst = sred + w * REDW;
#pragma unroll
            for (int mt = 0; mt < 2; mt++)
#pragma unroll
                for (int nt = 0; nt < 2; nt++) {
                    int r0 = 16 * mt + (l >> 2);
                    int c0 = 8 * nt + 2 * (l & 3);
                    dst[r0 * 34 + c0]           = aR[mt][nt][0];
                    dst[r0 * 34 + c0 + 1]       = aR[mt][nt][1];
                    dst[(r0 + 8) * 34 + c0]     = aR[mt][nt][2];
                    dst[(r0 + 8) * 34 + c0 + 1] = aR[mt][nt][3];
                }
        }
        __syncthreads();
        {
            int b = tid >> 3, n = (tid & 7) * 2;   // 32 rows x 16 cols, 2/thread
            float s0 = 0.0f, s1 = 0.0f;
#pragma unroll
            for (int ww = 0; ww < 8; ww++) {
                const float* src = sred + ww * REDW + b * 34 + n;
                s0 += src[0]; s1 += src[1];
            }
            sfin[b * SFS + n] = s0;
            sfin[b * SFS + n + 1] = s1;
        }
        __syncthreads();

        // elementwise A: r, rh
        {
            const float hp[2] = {hpv.x, hpv.y};
            const float xr[2] = {xrv.x, xrv.y};
            float rhv[2];
#pragma unroll
            for (int j = 0; j < 2; j++) {
                const float r = sigmoidf_(sfin[eb * SFS + ec0 + j] + xr[j]);
                rhv[j] = r * hp[j];
            }
            g_rhb[(size_t)gb * 512 + ((j0 + ec0) >> 1)] = pack_bf16(rhv[0], rhv[1]);
        }

        fsync();   // rh complete (this half)

        // ================= phase B: z (retained h) + hbar =================
        // issue rh bulk staging first; z-mma hides the copy latency
        stage_bulk(sA1u, g_rhb);

        float aZ[2][2][4];
#pragma unroll
        for (int mt = 0; mt < 2; mt++)
#pragma unroll
            for (int nt = 0; nt < 2; nt++)
#pragma unroll
                for (int r = 0; r < 4; r++) aZ[mt][nt][r] = 0.0f;

#pragma unroll
        for (int kt = 0; kt < 8; kt++) {
            const int ko = 64 * w + 8 * kt;
#pragma unroll
            for (int mt = 0; mt < 2; mt++) {
                const uint32_t* P = sA0 + (16 * mt + ar) * AST2 + ko + ac;
                uint32_t a[4];
                a[0] = P[0];
                a[1] = P[8 * AST2];
                a[2] = P[4];
                a[3] = P[8 * AST2 + 4];
#pragma unroll
                for (int nt = 0; nt < 2; nt++)
                    mma_bf16(aZ[mt][nt], a, bzf[kt][nt]);
            }
        }

        // reduce z -> sfin cols 16..31
        {
            float* dst = sred + w * REDW;
#pragma unroll
            for (int mt = 0; mt < 2; mt++)
#pragma unroll
                for (int nt = 0; nt < 2; nt++) {
                    int r0 = 16 * mt + (l >> 2);
                    int c0 = 8 * nt + 2 * (l & 3);
                    dst[r0 * 34 + c0]           = aZ[mt][nt][0];
                    dst[r0 * 34 + c0 + 1]       = aZ[mt][nt][1];
                    dst[(r0 + 8) * 34 + c0]     = aZ[mt][nt][2];
                    dst[(r0 + 8) * 34 + c0 + 1] = aZ[mt][nt][3];
                }
        }
        __syncthreads();
        {
            int b = tid >> 3, n = (tid & 7) * 2;
            float s0 = 0.0f, s1 = 0.0f;
#pragma unroll
            for (int ww = 0; ww < 8; ww++) {
                const float* src = sred + ww * REDW + b * 34 + n;
                s0 += src[0]; s1 += src[1];
            }
            sfin[b * SFS + 16 + n] = s0;
            sfin[b * SFS + 16 + n + 1] = s1;
        }

        // rh tile ready
        mbar_wait(mbar, mpar);  mpar ^= 1;
        __syncthreads();

        float aH[2][2][4];
#pragma unroll
        for (int mt = 0; mt < 2; mt++)
#pragma unroll
            for (int nt = 0; nt < 2; nt++)
#pragma unroll
                for (int r = 0; r < 4; r++) aH[mt][nt][r] = 0.0f;

#pragma unroll
        for (int kt = 0; kt < 8; kt++) {
            const int ko = 64 * w + 8 * kt;
#pragma unroll
            for (int mt = 0; mt < 2; mt++) {
                const uint32_t* P = sA1 + (16 * mt + ar) * AST2 + ko + ac;
                uint32_t a[4];
                a[0] = P[0];
                a[1] = P[8 * AST2];
                a[2] = P[4];
                a[3] = P[8 * AST2 + 4];
#pragma unroll
                for (int nt = 0; nt < 2; nt++)
                    mma_bf16(aH[mt][nt], a, bhf[kt][nt]);
            }
        }

        // reduce hbar -> sfin cols 0..15
        {
            float* dst = sred + w * REDW;
#pragma unroll
            for (int mt = 0; mt < 2; mt++)
#pragma unroll
                for (int nt = 0; nt < 2; nt++) {
                    int r0 = 16 * mt + (l >> 2);
                    int c0 = 8 * nt + 2 * (l & 3);
                    dst[r0 * 34 + c0]           = aH[mt][nt][0];
                    dst[r0 * 34 + c0 + 1]       = aH[mt][nt][1];
                    dst[(r0 + 8) * 34 + c0]     = aH[mt][nt][2];
                    dst[(r0 + 8) * 34 + c0 + 1] = aH[mt][nt][3];
                }
        }
        __syncthreads();
        {
            int b = tid >> 3, n = (tid & 7) * 2;
            float s0 = 0.0f, s1 = 0.0f;
#pragma unroll
            for (int ww = 0; ww < 8; ww++) {
                const float* src = sred + ww * REDW + b * 34 + n;
                s0 += src[0]; s1 += src[1];
            }
            sfin[b * SFS + n] = s0;
            sfin[b * SFS + n + 1] = s1;
        }
        __syncthreads();

        // elementwise B + output (fp32 state update)
        {
            const float hp[2] = {hpv.x, hpv.y};
            const float xz[2] = {xzv.x, xzv.y};
            const float xh[2] = {xhv.x, xhv.y};
            float hn[2];
#pragma unroll
            for (int j = 0; j < 2; j++) {
                const float z  = sigmoidf_(sfin[eb * SFS + 16 + ec0 + j] + xz[j]);
                const float hb = tanhf(sfin[eb * SFS + ec0 + j] + xh[j]);
                hn[j] = (1.0f - z) * hp[j] + z * hb;
            }
            float2 o; o.x = hn[0]; o.y = hn[1];
            *(float2*)&out[((size_t)gb * TT + t) * HID + j0 + ec0] = o;
            g_hb[(size_t)gb * 512 + ((j0 + ec0) >> 1)] = pack_bf16(hn[0], hn[1]);
            if (t == TT - 1)
                *(float2*)&out[(size_t)BSZ * TT * HID + (size_t)gb * HID + j0 + ec0] = o;
        }

        if (t + 1 < TT)
            fsync();   // h complete (this half)
    }
}

// =====================================================================
extern "C" void kernel_launch(void* const* d_in, const int* in_sizes, int n_in,
                              void* d_out, int out_size)
{
    const float* x  = (const float*)d_in[0];
    const float* h0 = (const float*)d_in[1];
    const float* wz = (const float*)d_in[2];
    const float* wr = (const float*)d_in[3];
    const float* wh = (const float*)d_in[4];
    const float* bz = (const float*)d_in[5];
    const float* br = (const float*)d_in[6];
    const float* bh = (const float*)d_in[7];
    float* out = (float*)d_out;

    const int x_smem = 4 * 64 * XS * sizeof(float);
    const int r_smem = (2 * 32 * AST2 + 8 * REDW + 32 * SFS) * sizeof(float) + 16;
    static bool attr_set = false;
    if (!attr_set) {
        cudaFuncSetAttribute(xproj_kernel,
                             cudaFuncAttributeMaxDynamicSharedMemorySize, x_smem);
        cudaFuncSetAttribute(recur_kernel,
                             cudaFuncAttributeMaxDynamicSharedMemorySize, r_smem);
        attr_set = true;
    }

    const int ysplit[4] = {0, 171, 342, 512};
    for (int s = 0; s < 3; s++) {
        dim3 g1(H3 / 64, ysplit[s + 1] - ysplit[s]);
        xproj_kernel<<<g1, 256, x_smem>>>(x, wz, wr, wh, bz, br, bh, ysplit[s]);
    }

    recur_kernel<<<128, 256, r_smem>>>(h0, wz, wr, wh, out);
}